// round 1
// baseline (speedup 1.0000x reference)
#include <cuda_runtime.h>
#include <cstdint>

// Problem constants
#define BB    128
#define CIN   96
#define HH    63
#define WW    63
#define COUT  256
#define KS    5
#define HO    30
#define WO    30
#define HID   24
#define TEMPR 31.0f

// Conv tiling
#define MTILE 64          // couts per block
#define OHT   6           // output rows per block
#define TX    30          // one thread per output col
#define TY    8
#define NTHR  (TX*TY)     // 240
#define COPT  (MTILE/TY)  // 8 couts per thread

// Scratch (device globals; no dynamic allocation allowed)
__device__ float g_pooled[BB * CIN];
__device__ float g_att[BB * 2];

// ---------------------------------------------------------------------------
// Kernel 1: global average pool  pooled[b][ci] = mean(x[b,ci,:,:])
// ---------------------------------------------------------------------------
__global__ void pool_kernel(const float* __restrict__ x) {
    const int ci = blockIdx.x;
    const int b  = blockIdx.y;
    const float* p = x + ((size_t)(b * CIN + ci)) * (HH * WW);
    float s = 0.f;
    for (int i = threadIdx.x; i < HH * WW; i += blockDim.x) s += p[i];
    __shared__ float red[32];
    #pragma unroll
    for (int o = 16; o; o >>= 1) s += __shfl_down_sync(0xffffffffu, s, o);
    if ((threadIdx.x & 31) == 0) red[threadIdx.x >> 5] = s;
    __syncthreads();
    if (threadIdx.x < 32) {
        s = (threadIdx.x < (blockDim.x >> 5)) ? red[threadIdx.x] : 0.f;
        #pragma unroll
        for (int o = 16; o; o >>= 1) s += __shfl_down_sync(0xffffffffu, s, o);
        if (threadIdx.x == 0) g_pooled[b * CIN + ci] = s * (1.0f / (HH * WW));
    }
}

// ---------------------------------------------------------------------------
// Kernel 2: attention MLP + softmax(logits / T).  One block, thread = sample.
// ---------------------------------------------------------------------------
__global__ void att_kernel(const float* __restrict__ w1,   // [24, 96]
                           const float* __restrict__ w2) { // [2, 24]
    const int b = threadIdx.x;   // 128 threads
    float pooled[CIN];
    #pragma unroll 8
    for (int i = 0; i < CIN; i++) pooled[i] = g_pooled[b * CIN + i];
    float l0 = 0.f, l1 = 0.f;
    for (int j = 0; j < HID; j++) {
        float h = 0.f;
        #pragma unroll 8
        for (int i = 0; i < CIN; i++) h += pooled[i] * w1[j * CIN + i];
        h = fmaxf(h, 0.f);
        l0 += h * w2[0 * HID + j];
        l1 += h * w2[1 * HID + j];
    }
    l0 *= (1.0f / TEMPR);
    l1 *= (1.0f / TEMPR);
    const float m  = fmaxf(l0, l1);
    const float e0 = __expf(l0 - m);
    const float e1 = __expf(l1 - m);
    const float inv = 1.0f / (e0 + e1);
    g_att[b * 2 + 0] = e0 * inv;
    g_att[b * 2 + 1] = e1 * inv;
}

// ---------------------------------------------------------------------------
// Kernel 3: per-sample mixed-weight 5x5 stride-2 conv (fp32 direct, smem tiled)
// Block: (b, 64 couts, 6 output rows x 30 cols). Thread: 8 couts x 6 rows.
// ---------------------------------------------------------------------------
__global__ void __launch_bounds__(NTHR)
conv_kernel(const float* __restrict__ x,
            const float* __restrict__ wc, const float* __restrict__ we,
            const float* __restrict__ cb, const float* __restrict__ eb,
            float* __restrict__ out)
{
    const int b   = blockIdx.x;
    const int co0 = blockIdx.y * MTILE;
    const int oh0 = blockIdx.z * OHT;
    const int ih0 = oh0 * 2;               // need rows ih0 .. ih0+14

    __shared__ float xs[15][64];           // 15 x 63 slab (padded)
    __shared__ float ws[MTILE][26];        // 64 couts x 25 taps (padded)

    const float a0 = g_att[b * 2 + 0];
    const float a1 = g_att[b * 2 + 1];

    const int tid = threadIdx.y * TX + threadIdx.x;
    const int wo  = threadIdx.x;

    float acc[COPT][OHT];
    #pragma unroll
    for (int c = 0; c < COPT; c++)
        #pragma unroll
        for (int r = 0; r < OHT; r++) acc[c][r] = 0.f;

    for (int ci = 0; ci < CIN; ci++) {
        __syncthreads();
        // stage input slab: 15 rows x 63 cols
        const float* xp = x + ((size_t)(b * CIN + ci) * HH + ih0) * WW;
        for (int i = tid; i < 15 * 63; i += NTHR) {
            const int r = i / 63, c = i - r * 63;
            xs[r][c] = xp[r * WW + c];
        }
        // stage + mix weight tile: 64 couts x 25 taps
        const size_t wbase = (size_t)co0 * (CIN * 25) + (size_t)ci * 25;
        for (int i = tid; i < MTILE * 25; i += NTHR) {
            const int c = i / 25, t = i - c * 25;
            const size_t off = wbase + (size_t)c * (CIN * 25) + t;
            ws[c][t] = a0 * wc[off] + a1 * we[off];
        }
        __syncthreads();

        #pragma unroll
        for (int kh = 0; kh < KS; kh++) {
            #pragma unroll
            for (int kw = 0; kw < KS; kw++) {
                float xv[OHT];
                #pragma unroll
                for (int r = 0; r < OHT; r++)
                    xv[r] = xs[2 * r + kh][2 * wo + kw];
                #pragma unroll
                for (int c = 0; c < COPT; c++) {
                    const float wv = ws[threadIdx.y + TY * c][kh * 5 + kw];
                    #pragma unroll
                    for (int r = 0; r < OHT; r++)
                        acc[c][r] += xv[r] * wv;
                }
            }
        }
    }

    // epilogue: add mixed bias, write out
    #pragma unroll
    for (int c = 0; c < COPT; c++) {
        const int co = co0 + threadIdx.y + TY * c;
        const float bias = a0 * cb[co] + a1 * eb[co];
        #pragma unroll
        for (int r = 0; r < OHT; r++) {
            out[(((size_t)b * COUT + co) * HO + (oh0 + r)) * WO + wo] =
                acc[c][r] + bias;
        }
    }
}

// ---------------------------------------------------------------------------
// Launch
// ---------------------------------------------------------------------------
extern "C" void kernel_launch(void* const* d_in, const int* in_sizes, int n_in,
                              void* d_out, int out_size) {
    (void)in_sizes; (void)n_in; (void)out_size;
    const float* x  = (const float*)d_in[0];
    const float* wc = (const float*)d_in[1];
    const float* cb = (const float*)d_in[2];
    const float* we = (const float*)d_in[3];
    const float* eb = (const float*)d_in[4];
    const float* w1 = (const float*)d_in[5];
    const float* w2 = (const float*)d_in[6];
    float* out = (float*)d_out;

    pool_kernel<<<dim3(CIN, BB), 256>>>(x);
    att_kernel<<<1, BB>>>(w1, w2);
    conv_kernel<<<dim3(BB, COUT / MTILE, HO / OHT), dim3(TX, TY)>>>(
        x, wc, we, cb, eb, out);
}

// round 2
// speedup vs baseline: 1.0036x; 1.0036x over previous
#include <cuda_runtime.h>
#include <cstdint>

// Problem constants
#define BB    128
#define CIN   96
#define HH    63
#define WW    63
#define COUT  256
#define KS    5
#define HO    30
#define WO    30
#define HID   24
#define TEMPR 31.0f

// Conv tiling
#define MTILE 64          // couts per block
#define OHT   6           // output rows per block
#define TX    30          // one thread per output col
#define TY    8
#define NTHR  (TX*TY)     // 240
#define COPT  (MTILE/TY)  // 8 couts per thread

// Scratch (device globals; no dynamic allocation allowed)
__device__ float g_pooled[BB * CIN];
__device__ float g_att[BB * 2];

// ---------------------------------------------------------------------------
// Kernel 1: global average pool  pooled[b][ci] = mean(x[b,ci,:,:])
// ---------------------------------------------------------------------------
__global__ void pool_kernel(const float* __restrict__ x) {
    const int ci = blockIdx.x;
    const int b  = blockIdx.y;
    const float* p = x + ((size_t)(b * CIN + ci)) * (HH * WW);
    float s = 0.f;
    for (int i = threadIdx.x; i < HH * WW; i += blockDim.x) s += p[i];
    __shared__ float red[32];
    #pragma unroll
    for (int o = 16; o; o >>= 1) s += __shfl_down_sync(0xffffffffu, s, o);
    if ((threadIdx.x & 31) == 0) red[threadIdx.x >> 5] = s;
    __syncthreads();
    if (threadIdx.x < 32) {
        s = (threadIdx.x < (blockDim.x >> 5)) ? red[threadIdx.x] : 0.f;
        #pragma unroll
        for (int o = 16; o; o >>= 1) s += __shfl_down_sync(0xffffffffu, s, o);
        if (threadIdx.x == 0) g_pooled[b * CIN + ci] = s * (1.0f / (HH * WW));
    }
}

// ---------------------------------------------------------------------------
// Kernel 2: attention MLP + softmax(logits / T).  One block, thread = sample.
// ---------------------------------------------------------------------------
__global__ void att_kernel(const float* __restrict__ w1,   // [24, 96]
                           const float* __restrict__ w2) { // [2, 24]
    const int b = threadIdx.x;   // 128 threads
    float pooled[CIN];
    #pragma unroll 8
    for (int i = 0; i < CIN; i++) pooled[i] = g_pooled[b * CIN + i];
    float l0 = 0.f, l1 = 0.f;
    for (int j = 0; j < HID; j++) {
        float h = 0.f;
        #pragma unroll 8
        for (int i = 0; i < CIN; i++) h += pooled[i] * w1[j * CIN + i];
        h = fmaxf(h, 0.f);
        l0 += h * w2[0 * HID + j];
        l1 += h * w2[1 * HID + j];
    }
    l0 *= (1.0f / TEMPR);
    l1 *= (1.0f / TEMPR);
    const float m  = fmaxf(l0, l1);
    const float e0 = __expf(l0 - m);
    const float e1 = __expf(l1 - m);
    const float inv = 1.0f / (e0 + e1);
    g_att[b * 2 + 0] = e0 * inv;
    g_att[b * 2 + 1] = e1 * inv;
}

// ---------------------------------------------------------------------------
// Kernel 3: per-sample mixed-weight 5x5 stride-2 conv (fp32 direct, smem tiled)
// Block: (b, 64 couts, 6 output rows x 30 cols). Thread: 8 couts x 6 rows.
// ---------------------------------------------------------------------------
__global__ void __launch_bounds__(NTHR)
conv_kernel(const float* __restrict__ x,
            const float* __restrict__ wc, const float* __restrict__ we,
            const float* __restrict__ cb, const float* __restrict__ eb,
            float* __restrict__ out)
{
    const int b   = blockIdx.x;
    const int co0 = blockIdx.y * MTILE;
    const int oh0 = blockIdx.z * OHT;
    const int ih0 = oh0 * 2;               // need rows ih0 .. ih0+14

    __shared__ float xs[15][64];           // 15 x 63 slab (padded)
    __shared__ float ws[MTILE][26];        // 64 couts x 25 taps (padded)

    const float a0 = g_att[b * 2 + 0];
    const float a1 = g_att[b * 2 + 1];

    const int tid = threadIdx.y * TX + threadIdx.x;
    const int wo  = threadIdx.x;

    float acc[COPT][OHT];
    #pragma unroll
    for (int c = 0; c < COPT; c++)
        #pragma unroll
        for (int r = 0; r < OHT; r++) acc[c][r] = 0.f;

    for (int ci = 0; ci < CIN; ci++) {
        __syncthreads();
        // stage input slab: 15 rows x 63 cols
        const float* xp = x + ((size_t)(b * CIN + ci) * HH + ih0) * WW;
        for (int i = tid; i < 15 * 63; i += NTHR) {
            const int r = i / 63, c = i - r * 63;
            xs[r][c] = xp[r * WW + c];
        }
        // stage + mix weight tile: 64 couts x 25 taps
        const size_t wbase = (size_t)co0 * (CIN * 25) + (size_t)ci * 25;
        for (int i = tid; i < MTILE * 25; i += NTHR) {
            const int c = i / 25, t = i - c * 25;
            const size_t off = wbase + (size_t)c * (CIN * 25) + t;
            ws[c][t] = a0 * wc[off] + a1 * we[off];
        }
        __syncthreads();

        #pragma unroll
        for (int kh = 0; kh < KS; kh++) {
            #pragma unroll
            for (int kw = 0; kw < KS; kw++) {
                float xv[OHT];
                #pragma unroll
                for (int r = 0; r < OHT; r++)
                    xv[r] = xs[2 * r + kh][2 * wo + kw];
                #pragma unroll
                for (int c = 0; c < COPT; c++) {
                    const float wv = ws[threadIdx.y + TY * c][kh * 5 + kw];
                    #pragma unroll
                    for (int r = 0; r < OHT; r++)
                        acc[c][r] += xv[r] * wv;
                }
            }
        }
    }

    // epilogue: add mixed bias, write out
    #pragma unroll
    for (int c = 0; c < COPT; c++) {
        const int co = co0 + threadIdx.y + TY * c;
        const float bias = a0 * cb[co] + a1 * eb[co];
        #pragma unroll
        for (int r = 0; r < OHT; r++) {
            out[(((size_t)b * COUT + co) * HO + (oh0 + r)) * WO + wo] =
                acc[c][r] + bias;
        }
    }
}

// ---------------------------------------------------------------------------
// Launch
// ---------------------------------------------------------------------------
extern "C" void kernel_launch(void* const* d_in, const int* in_sizes, int n_in,
                              void* d_out, int out_size) {
    (void)in_sizes; (void)n_in; (void)out_size;
    const float* x  = (const float*)d_in[0];
    const float* wc = (const float*)d_in[1];
    const float* cb = (const float*)d_in[2];
    const float* we = (const float*)d_in[3];
    const float* eb = (const float*)d_in[4];
    const float* w1 = (const float*)d_in[5];
    const float* w2 = (const float*)d_in[6];
    float* out = (float*)d_out;

    pool_kernel<<<dim3(CIN, BB), 256>>>(x);
    att_kernel<<<1, BB>>>(w1, w2);
    conv_kernel<<<dim3(BB, COUT / MTILE, HO / OHT), dim3(TX, TY)>>>(
        x, wc, we, cb, eb, out);
}

// round 4
// speedup vs baseline: 3.2271x; 3.2156x over previous
#include <cuda_runtime.h>
#include <cstdint>

// ---------------------------------------------------------------------------
// Problem constants
// ---------------------------------------------------------------------------
#define BB    128
#define CIN   96
#define HH    63
#define WW    63
#define COUT  256
#define HO    30
#define WO    30
#define HID   24
#define TEMPR 31.0f

#define KDIM  2400          // Cin * 25
#define PDIM  900           // Ho * Wo
#define PPAD  1024

// GEMM tiling
#define KSTEP   16
#define NKIT    (KDIM / KSTEP)   // 150
#define MT      128              // cout per CTA
#define NT      128              // p per CTA
#define STAGES  5
#define ROWPAD  20               // smem row stride (floats), conflict-free frags
#define ATILE_F (MT * ROWPAD)    // 2560 floats
#define STAGE_F (2 * ATILE_F)    // A + B
#define SMEM_B  (STAGES * STAGE_F * 4)   // 102400 bytes

// ---------------------------------------------------------------------------
// Device scratch
// ---------------------------------------------------------------------------
__device__ float g_pooled[BB * CIN];
__device__ float g_att[BB * 2];
__device__ float g_w[(size_t)BB * COUT * KDIM];   // mixed weight, tf32-rounded
__device__ float g_x[(size_t)BB * PPAD * KDIM];   // im2col,     tf32-rounded

// ---------------------------------------------------------------------------
// Helpers
// ---------------------------------------------------------------------------
__device__ __forceinline__ float to_tf32(float v) {
    uint32_t o;
    asm("cvt.rna.tf32.f32 %0, %1;" : "=r"(o) : "f"(v));
    return __uint_as_float(o);
}

__device__ __forceinline__ uint32_t smem_u32(const void* p) {
    uint32_t a;
    asm("{ .reg .u64 t; cvta.to.shared.u64 t, %1; cvt.u32.u64 %0, t; }"
        : "=r"(a) : "l"(p));
    return a;
}

__device__ __forceinline__ void cp16(uint32_t dst, const float* src) {
    asm volatile("cp.async.cg.shared.global [%0], [%1], 16;"
                 :: "r"(dst), "l"(src) : "memory");
}
__device__ __forceinline__ void cp_commit() {
    asm volatile("cp.async.commit_group;" ::: "memory");
}
__device__ __forceinline__ void cp_wait3() {
    asm volatile("cp.async.wait_group 3;" ::: "memory");
}

__device__ __forceinline__ void mma_tf32(float* d, const uint32_t* a,
                                         const uint32_t* b) {
    asm volatile(
        "mma.sync.aligned.m16n8k8.row.col.f32.tf32.tf32.f32 "
        "{%0,%1,%2,%3}, {%4,%5,%6,%7}, {%8,%9}, {%0,%1,%2,%3};"
        : "+f"(d[0]), "+f"(d[1]), "+f"(d[2]), "+f"(d[3])
        : "r"(a[0]), "r"(a[1]), "r"(a[2]), "r"(a[3]), "r"(b[0]), "r"(b[1]));
}

// ---------------------------------------------------------------------------
// Kernel 1: global average pool
// ---------------------------------------------------------------------------
__global__ void pool_kernel(const float* __restrict__ x) {
    const int ci = blockIdx.x;
    const int b  = blockIdx.y;
    const float* p = x + ((size_t)(b * CIN + ci)) * (HH * WW);
    float s = 0.f;
    for (int i = threadIdx.x; i < HH * WW; i += blockDim.x) s += p[i];
    __shared__ float red[32];
    #pragma unroll
    for (int o = 16; o; o >>= 1) s += __shfl_down_sync(0xffffffffu, s, o);
    if ((threadIdx.x & 31) == 0) red[threadIdx.x >> 5] = s;
    __syncthreads();
    if (threadIdx.x < 32) {
        s = (threadIdx.x < (blockDim.x >> 5)) ? red[threadIdx.x] : 0.f;
        #pragma unroll
        for (int o = 16; o; o >>= 1) s += __shfl_down_sync(0xffffffffu, s, o);
        if (threadIdx.x == 0) g_pooled[b * CIN + ci] = s * (1.0f / (HH * WW));
    }
}

// ---------------------------------------------------------------------------
// Kernel 2: attention MLP + softmax
// ---------------------------------------------------------------------------
__global__ void att_kernel(const float* __restrict__ w1,
                           const float* __restrict__ w2) {
    const int b = threadIdx.x;
    float pooled[CIN];
    #pragma unroll 8
    for (int i = 0; i < CIN; i++) pooled[i] = g_pooled[b * CIN + i];
    float l0 = 0.f, l1 = 0.f;
    for (int j = 0; j < HID; j++) {
        float h = 0.f;
        #pragma unroll 8
        for (int i = 0; i < CIN; i++) h += pooled[i] * w1[j * CIN + i];
        h = fmaxf(h, 0.f);
        l0 += h * w2[0 * HID + j];
        l1 += h * w2[1 * HID + j];
    }
    l0 *= (1.0f / TEMPR);
    l1 *= (1.0f / TEMPR);
    const float m  = fmaxf(l0, l1);
    const float e0 = __expf(l0 - m);
    const float e1 = __expf(l1 - m);
    const float inv = 1.0f / (e0 + e1);
    g_att[b * 2 + 0] = e0 * inv;
    g_att[b * 2 + 1] = e1 * inv;
}

// ---------------------------------------------------------------------------
// Kernel 3: mixed weight -> tf32-rounded fp32
// ---------------------------------------------------------------------------
__global__ void wmix_kernel(const float* __restrict__ wc,
                            const float* __restrict__ we) {
    const int co = blockIdx.x;
    const int b  = blockIdx.y;
    const float a0 = g_att[2 * b], a1 = g_att[2 * b + 1];
    float* dst = g_w + ((size_t)b * COUT + co) * KDIM;
    const float* pc = wc + (size_t)co * KDIM;
    const float* pe = we + (size_t)co * KDIM;
    for (int k = threadIdx.x; k < KDIM; k += blockDim.x)
        dst[k] = to_tf32(a0 * pc[k] + a1 * pe[k]);
}

// ---------------------------------------------------------------------------
// Kernel 4: im2col -> tf32-rounded fp32.  Row = (b, p), K-major.
// Rows p >= 900 never written (stay zero) -> their GEMM cols are discarded.
// ---------------------------------------------------------------------------
__global__ void im2col_kernel(const float* __restrict__ x) {
    const int p = blockIdx.x;           // 0..899
    const int b = blockIdx.y;
    const int oh = p / WO, ow = p - oh * WO;
    const float* xb = x + (size_t)b * CIN * HH * WW + (size_t)(oh * 2) * WW + ow * 2;
    float* dst = g_x + ((size_t)b * PPAD + p) * KDIM;
    for (int k = threadIdx.x; k < KDIM; k += blockDim.x) {
        const int ci = k / 25, t = k - ci * 25;
        const int kh = t / 5, kw = t - kh * 5;
        dst[k] = to_tf32(xb[(ci * HH + kh) * WW + kw]);
    }
}

// ---------------------------------------------------------------------------
// Kernel 5: tf32 mma.sync GEMM.
// CTA = (b, co_tile 128, p_tile 128).  8 warps, 64x32 per warp.
// 5-stage cp.async pipeline over 150 K-iterations of 16.
// ---------------------------------------------------------------------------
__global__ void __launch_bounds__(256, 2)
gemm_kernel(const float* __restrict__ cb, const float* __restrict__ eb,
            float* __restrict__ out)
{
    extern __shared__ float sm[];
    const int b   = blockIdx.y;
    const int ct  = blockIdx.x >> 3;          // 0..1  (co tile)
    const int pt  = blockIdx.x & 7;           // 0..7  (p tile)
    const int co0 = ct * MT;
    const int p0  = pt * NT;

    const int tid  = threadIdx.x;
    const int wid  = tid >> 5;
    const int lane = tid & 31;
    const int wm   = wid & 1;                 // warp M (2)
    const int wn   = wid >> 1;                // warp N (4)
    const int g    = lane >> 2;               // group 0..7
    const int t    = lane & 3;

    const float* gA = g_w + ((size_t)b * COUT + co0) * KDIM;
    const float* gB = g_x + ((size_t)b * PPAD + p0) * KDIM;

    const uint32_t smbase = smem_u32(sm);
    // per-thread staging chunks: A chunks tid, tid+256; same for B
    const int r0c = tid >> 2,        s0c = tid & 3;         // chunk tid
    const int r1c = (tid + 256) >> 2, s1c = tid & 3;        // chunk tid+256

    float acc[4][4][4];
    #pragma unroll
    for (int m = 0; m < 4; m++)
        #pragma unroll
        for (int n = 0; n < 4; n++)
            #pragma unroll
            for (int r = 0; r < 4; r++) acc[m][n][r] = 0.f;

    // ---- prologue: stage 0..2 ----
    #pragma unroll
    for (int s = 0; s < 3; s++) {
        const int k0 = s * KSTEP;
        const uint32_t abase = smbase + (uint32_t)(s * STAGE_F) * 4;
        const uint32_t bbase = abase + ATILE_F * 4;
        cp16(abase + (uint32_t)(r0c * ROWPAD + s0c * 4) * 4, gA + (size_t)r0c * KDIM + k0 + s0c * 4);
        cp16(abase + (uint32_t)(r1c * ROWPAD + s1c * 4) * 4, gA + (size_t)r1c * KDIM + k0 + s1c * 4);
        cp16(bbase + (uint32_t)(r0c * ROWPAD + s0c * 4) * 4, gB + (size_t)r0c * KDIM + k0 + s0c * 4);
        cp16(bbase + (uint32_t)(r1c * ROWPAD + s1c * 4) * 4, gB + (size_t)r1c * KDIM + k0 + s1c * 4);
        cp_commit();
    }

    // ---- main loop ----
    for (int it = 0; it < NKIT; it++) {
        // issue stage it+3
        if (it + 3 < NKIT) {
            const int s = (it + 3) % STAGES;
            const int k0 = (it + 3) * KSTEP;
            const uint32_t abase = smbase + (uint32_t)(s * STAGE_F) * 4;
            const uint32_t bbase = abase + ATILE_F * 4;
            cp16(abase + (uint32_t)(r0c * ROWPAD + s0c * 4) * 4, gA + (size_t)r0c * KDIM + k0 + s0c * 4);
            cp16(abase + (uint32_t)(r1c * ROWPAD + s1c * 4) * 4, gA + (size_t)r1c * KDIM + k0 + s1c * 4);
            cp16(bbase + (uint32_t)(r0c * ROWPAD + s0c * 4) * 4, gB + (size_t)r0c * KDIM + k0 + s0c * 4);
            cp16(bbase + (uint32_t)(r1c * ROWPAD + s1c * 4) * 4, gB + (size_t)r1c * KDIM + k0 + s1c * 4);
        }
        cp_commit();
        cp_wait3();
        __syncthreads();

        const float* As = sm + (it % STAGES) * STAGE_F;
        const float* Bs = As + ATILE_F;

        #pragma unroll
        for (int kk = 0; kk < 2; kk++) {
            const int c0 = kk * 8 + t;
            uint32_t afr[4][4];
            #pragma unroll
            for (int m = 0; m < 4; m++) {
                const int r = wm * 64 + m * 16 + g;
                afr[m][0] = __float_as_uint(As[r * ROWPAD + c0]);
                afr[m][1] = __float_as_uint(As[(r + 8) * ROWPAD + c0]);
                afr[m][2] = __float_as_uint(As[r * ROWPAD + c0 + 4]);
                afr[m][3] = __float_as_uint(As[(r + 8) * ROWPAD + c0 + 4]);
            }
            uint32_t bfr[4][2];
            #pragma unroll
            for (int n = 0; n < 4; n++) {
                const int col = wn * 32 + n * 8 + g;
                bfr[n][0] = __float_as_uint(Bs[col * ROWPAD + c0]);
                bfr[n][1] = __float_as_uint(Bs[col * ROWPAD + c0 + 4]);
            }
            #pragma unroll
            for (int m = 0; m < 4; m++)
                #pragma unroll
                for (int n = 0; n < 4; n++)
                    mma_tf32(acc[m][n], afr[m], bfr[n]);
        }
        __syncthreads();
    }

    // ---- epilogue ----
    const float a0 = g_att[2 * b], a1 = g_att[2 * b + 1];
    #pragma unroll
    for (int m = 0; m < 4; m++) {
        const int co_lo = co0 + wm * 64 + m * 16 + g;
        const int co_hi = co_lo + 8;
        const float bias_lo = a0 * cb[co_lo] + a1 * eb[co_lo];
        const float bias_hi = a0 * cb[co_hi] + a1 * eb[co_hi];
        float* op_lo = out + ((size_t)b * COUT + co_lo) * PDIM;
        float* op_hi = out + ((size_t)b * COUT + co_hi) * PDIM;
        #pragma unroll
        for (int n = 0; n < 4; n++) {
            const int p = p0 + wn * 32 + n * 8 + t * 2;   // even
            if (p < PDIM) {
                float2 v0 = make_float2(acc[m][n][0] + bias_lo, acc[m][n][1] + bias_lo);
                float2 v1 = make_float2(acc[m][n][2] + bias_hi, acc[m][n][3] + bias_hi);
                *(float2*)(op_lo + p) = v0;
                *(float2*)(op_hi + p) = v1;
            }
        }
    }
}

// ---------------------------------------------------------------------------
// Host launch
// ---------------------------------------------------------------------------
extern "C" void kernel_launch(void* const* d_in, const int* in_sizes, int n_in,
                              void* d_out, int out_size) {
    (void)in_sizes; (void)n_in; (void)out_size;
    const float* x  = (const float*)d_in[0];
    const float* wc = (const float*)d_in[1];
    const float* cb = (const float*)d_in[2];
    const float* we = (const float*)d_in[3];
    const float* eb = (const float*)d_in[4];
    const float* w1 = (const float*)d_in[5];
    const float* w2 = (const float*)d_in[6];
    float* out = (float*)d_out;

    pool_kernel<<<dim3(CIN, BB), 256>>>(x);
    att_kernel<<<1, BB>>>(w1, w2);
    wmix_kernel<<<dim3(COUT, BB), 256>>>(wc, we);
    im2col_kernel<<<dim3(PDIM, BB), 256>>>(x);

    static bool attr_set = false;
    if (!attr_set) {
        cudaFuncSetAttribute(gemm_kernel,
                             cudaFuncAttributeMaxDynamicSharedMemorySize, SMEM_B);
        attr_set = true;
    }
    gemm_kernel<<<dim3(16, BB), 256, SMEM_B>>>(cb, eb, out);
}